// round 3
// baseline (speedup 1.0000x reference)
#include <cuda_runtime.h>
#include <math.h>

#define DIN 1024
#define D   256
#define DG  128
#define DB  64
#define NL1 8
#define NL2 32
#define BATCH 16
#define TLEN 2048
#define MROWS (BATCH*TLEN)

__device__ float g_U[MROWS*D];
__device__ float g_gin[BATCH*DIN];
__device__ int   g_idx1[BATCH];
__device__ float g_Wc[DB*D];
__device__ float g_bc[DB];
__device__ float g_nck[NL1*NL2*DB];
__device__ float g_snck[NL1*NL2];
__device__ float g_Mall[NL1*D*NL2];
__device__ float g_dall[NL1*NL2];
__device__ float g_table[NL1*NL2*D];

__device__ __forceinline__ void blockLN256(float v, int tid, float* sred,
                                           float& mean, float& rinv) {
    __syncthreads();
    float s = v, q = v*v;
#pragma unroll
    for (int off = 16; off; off >>= 1) {
        s += __shfl_xor_sync(0xffffffffu, s, off);
        q += __shfl_xor_sync(0xffffffffu, q, off);
    }
    if ((tid & 31) == 0) { sred[tid >> 5] = s; sred[8 + (tid >> 5)] = q; }
    __syncthreads();
    float ts = 0.f, tq = 0.f;
#pragma unroll
    for (int w = 0; w < 8; w++) { ts += sred[w]; tq += sred[8 + w]; }
    mean = ts * (1.f / 256.f);
    float var = tq * (1.f / 256.f) - mean * mean;
    rinv = rsqrtf(fmaxf(var, 0.f) + 1e-5f);
}

__global__ void k_wc(const float* __restrict__ Wtb, const float* __restrict__ Wl2,
                     const float* __restrict__ bl2, const float* __restrict__ btb) {
    __shared__ float sw[D];
    int i = blockIdx.x, j = threadIdx.x;
    sw[j] = Wtb[i*D + j];
    __syncthreads();
    float acc = 0.f;
#pragma unroll 4
    for (int r = 0; r < D; r++) acc += sw[r] * Wl2[r*D + j];
    g_Wc[i*D + j] = acc;
    if (j == 0) {
        float a = btb[i];
        for (int r = 0; r < D; r++) a += sw[r] * bl2[r];
        g_bc[i] = a;
    }
}

__global__ void k_nck(const float* __restrict__ cb2) {
    __shared__ float sred[4];
    int bk = blockIdx.x, t = threadIdx.x;
    float v = cb2[bk*DB + t];
    float q = v*v;
#pragma unroll
    for (int off = 16; off; off >>= 1) q += __shfl_xor_sync(0xffffffffu, q, off);
    if ((t & 31) == 0) sred[t >> 5] = q;
    __syncthreads();
    float nrm = sqrtf(sred[0] + sred[1]);
    float nv = v / fmaxf(nrm, 1e-12f);
    g_nck[bk*DB + t] = nv;
    float s = nv;
#pragma unroll
    for (int off = 16; off; off >>= 1) s += __shfl_xor_sync(0xffffffffu, s, off);
    if ((t & 31) == 0) sred[2 + (t >> 5)] = s;
    __syncthreads();
    if (t == 0) g_snck[bk] = sred[2] + sred[3];
}

__global__ void k_Md() {
    __shared__ float sN[NL2*65];
    int i = blockIdx.x, tid = threadIdx.x;
    int k = tid & 31, cl = tid >> 5;
    int c = blockIdx.y * 8 + cl;
    for (int t = tid; t < NL2*DB; t += 256) {
        int kk = t / DB, rr = t % DB;
        sN[kk*65 + rr] = g_nck[i*NL2*DB + t];
    }
    __syncthreads();
    float acc = 0.f, cs = 0.f;
#pragma unroll 4
    for (int r = 0; r < DB; r++) {
        float wv = g_Wc[r*D + c];
        acc += wv * sN[k*65 + r];
        cs  += wv;
    }
    float sn = g_snck[i*NL2 + k];
    g_Mall[i*(D*NL2) + c*NL2 + k] = acc - cs * sn * (1.f/DB);
    if (blockIdx.y == 0 && cl == 0) {
        float dv = 0.f, bs = 0.f;
        for (int r = 0; r < DB; r++) {
            float b = g_bc[r];
            dv += b * sN[k*65 + r];
            bs += b;
        }
        g_dall[i*NL2 + k] = dv - bs * (1.f/DB) * sn;
    }
}

__global__ void k_table(const float* __restrict__ cb2, const float* __restrict__ Wfb,
                        const float* __restrict__ bfb, const float* __restrict__ cb1,
                        const float* __restrict__ Wf,  const float* __restrict__ bf) {
    __shared__ float se[DB];
    __shared__ float sl[D];
    __shared__ float sc1[DG];
    __shared__ float sred[16];
    int bid = blockIdx.x;
    int i = bid >> 5;
    int j = threadIdx.x;
    if (j < DB) se[j] = cb2[bid*DB + j];
    if (j >= 128) sc1[j - 128] = cb1[i*DG + (j - 128)];
    __syncthreads();
    float a = bfb[j];
    const float* w = Wfb + (size_t)j * DB;
#pragma unroll 4
    for (int r = 0; r < DB; r++) a += se[r] * w[r];
    float mean, rinv;
    blockLN256(a, j, sred, mean, rinv);
    sl[j] = (a - mean) * rinv;
    __syncthreads();
    float o = bf[j];
    const float* wf = Wf + (size_t)j * (D + DG);
#pragma unroll 4
    for (int r = 0; r < D; r++) o += sl[r] * wf[r];
#pragma unroll 4
    for (int r = 0; r < DG; r++) o += sc1[r] * wf[D + r];
    blockLN256(o, j, sred, mean, rinv);
    g_table[bid*D + j] = fmaxf((o - mean) * rinv, 0.f);
}

__global__ void k_ginstats(const float* __restrict__ x) {
    int b = blockIdx.x >> 2;
    int d = ((blockIdx.x & 3) << 8) + threadIdx.x;
    const float* p = x + (size_t)b * TLEN * DIN + d;
    float s = 0.f, q = 0.f;
    for (int t = 0; t < TLEN; t++) {
        float v = p[(size_t)t * DIN];
        s += v; q += v * v;
    }
    float mean = s * (1.f / TLEN);
    float var = (q - s * s * (1.f / TLEN)) * (1.f / (TLEN - 1));
    g_gin[b*DIN + d] = mean + sqrtf(fmaxf(var, 0.f));
}

__global__ void k_global(const float* __restrict__ Wg1, const float* __restrict__ bg1,
                         const float* __restrict__ Wg2, const float* __restrict__ bg2,
                         const float* __restrict__ Wp,  const float* __restrict__ bp,
                         const float* __restrict__ cb1) {
    __shared__ float sg[DIN];
    __shared__ float sh[D];
    __shared__ float sgp[DG];
    __shared__ float sz[DG];
    __shared__ float sred[16];
    __shared__ float slog[NL1];
    int b = blockIdx.x, j = threadIdx.x;
    for (int t = j; t < DIN; t += 256) sg[t] = g_gin[b*DIN + t];
    __syncthreads();
    float a = bg1[j];
    const float* wr = Wg1 + (size_t)j * DIN;
#pragma unroll 4
    for (int r = 0; r < DIN; r++) a += sg[r] * wr[r];
    float mean, rinv;
    blockLN256(a, j, sred, mean, rinv);
    sh[j] = fmaxf((a - mean) * rinv, 0.f);
    __syncthreads();
    if (j < DG) {
        float g2 = bg2[j];
        const float* w2 = Wg2 + (size_t)j * D;
#pragma unroll 4
        for (int r = 0; r < D; r++) g2 += sh[r] * w2[r];
        sgp[j] = g2;
    }
    __syncthreads();
    if (j < DG) {
        float z = bp[j];
        const float* wp = Wp + (size_t)j * DG;
#pragma unroll 4
        for (int r = 0; r < DG; r++) z += sgp[r] * wp[r];
        sz[j] = z;
    }
    __syncthreads();
    {
        float zv = (j < DG) ? sz[j] : 0.f;
        float s = zv;
#pragma unroll
        for (int off = 16; off; off >>= 1) s += __shfl_xor_sync(0xffffffffu, s, off);
        if ((j & 31) == 0) sred[j >> 5] = s;
        __syncthreads();
    }
    float meanz = (sred[0]+sred[1]+sred[2]+sred[3]+sred[4]+sred[5]+sred[6]+sred[7]) * (1.f/DG);
    if (j < NL1) {
        float dz = 0.f, cs = 0.f, nn = 0.f;
        const float* cr = cb1 + j*DG;
        for (int r = 0; r < DG; r++) {
            float cv = cr[r];
            dz += sz[r]*cv; cs += cv; nn += cv*cv;
        }
        slog[j] = (dz - meanz*cs) / fmaxf(sqrtf(nn), 1e-12f);
    }
    __syncthreads();
    if (j == 0) {
        float best = slog[0]; int bi = 0;
        for (int t = 1; t < NL1; t++) if (slog[t] > best) { best = slog[t]; bi = t; }
        g_idx1[b] = bi;
    }
}

// u = x @ Wl1.T + bl1 ; M=32768,N=256,K=1024 ; 128x128x16 tiles, 8x8/thread
__global__ __launch_bounds__(256, 2)
void k_sgemm(const float* __restrict__ A, const float* __restrict__ Bm,
             const float* __restrict__ bias) {
    __shared__ float As[2][16][128];
    __shared__ float Bs[2][16][128];
    const int K = DIN;
    int tid = threadIdx.x;
    int lr = tid >> 2;
    int lk = (tid & 3) << 2;
    const float* Ap = A  + (size_t)(blockIdx.y * 128) * K;
    const float* Bp = Bm + (size_t)(blockIdx.x * 128) * K;
    int tx = tid & 15, ty = tid >> 4;
    int ar0 = ty * 4, ar1 = 64 + ty * 4;
    int bc0 = tx * 4, bc1 = 64 + tx * 4;
    float acc[8][8];
#pragma unroll
    for (int i = 0; i < 8; i++)
#pragma unroll
        for (int jj = 0; jj < 8; jj++) acc[i][jj] = 0.f;

    float4 ra0, ra1, rb0, rb1;
    ra0 = *(const float4*)(Ap + (size_t)lr * K + lk);
    ra1 = *(const float4*)(Ap + (size_t)(lr + 64) * K + lk);
    rb0 = *(const float4*)(Bp + (size_t)lr * K + lk);
    rb1 = *(const float4*)(Bp + (size_t)(lr + 64) * K + lk);
    As[0][lk+0][lr]    = ra0.x; As[0][lk+1][lr]    = ra0.y; As[0][lk+2][lr]    = ra0.z; As[0][lk+3][lr]    = ra0.w;
    As[0][lk+0][lr+64] = ra1.x; As[0][lk+1][lr+64] = ra1.y; As[0][lk+2][lr+64] = ra1.z; As[0][lk+3][lr+64] = ra1.w;
    Bs[0][lk+0][lr]    = rb0.x; Bs[0][lk+1][lr]    = rb0.y; Bs[0][lk+2][lr]    = rb0.z; Bs[0][lk+3][lr]    = rb0.w;
    Bs[0][lk+0][lr+64] = rb1.x; Bs[0][lk+1][lr+64] = rb1.y; Bs[0][lk+2][lr+64] = rb1.z; Bs[0][lk+3][lr+64] = rb1.w;
    __syncthreads();

    for (int kt = 0; kt < 64; kt++) {
        int cur = kt & 1;
        if (kt < 63) {
            const float* Ak = Ap + (kt + 1) * 16 + lk;
            const float* Bk = Bp + (kt + 1) * 16 + lk;
            ra0 = *(const float4*)(Ak + (size_t)lr * K);
            ra1 = *(const float4*)(Ak + (size_t)(lr + 64) * K);
            rb0 = *(const float4*)(Bk + (size_t)lr * K);
            rb1 = *(const float4*)(Bk + (size_t)(lr + 64) * K);
        }
#pragma unroll
        for (int kk = 0; kk < 16; kk++) {
            float4 fa0 = *(const float4*)&As[cur][kk][ar0];
            float4 fa1 = *(const float4*)&As[cur][kk][ar1];
            float4 fb0 = *(const float4*)&Bs[cur][kk][bc0];
            float4 fb1 = *(const float4*)&Bs[cur][kk][bc1];
            float av[8] = {fa0.x, fa0.y, fa0.z, fa0.w, fa1.x, fa1.y, fa1.z, fa1.w};
            float bv[8] = {fb0.x, fb0.y, fb0.z, fb0.w, fb1.x, fb1.y, fb1.z, fb1.w};
#pragma unroll
            for (int i = 0; i < 8; i++)
#pragma unroll
                for (int jj = 0; jj < 8; jj++) acc[i][jj] += av[i] * bv[jj];
        }
        if (kt < 63) {
            int nxt = cur ^ 1;
            As[nxt][lk+0][lr]    = ra0.x; As[nxt][lk+1][lr]    = ra0.y; As[nxt][lk+2][lr]    = ra0.z; As[nxt][lk+3][lr]    = ra0.w;
            As[nxt][lk+0][lr+64] = ra1.x; As[nxt][lk+1][lr+64] = ra1.y; As[nxt][lk+2][lr+64] = ra1.z; As[nxt][lk+3][lr+64] = ra1.w;
            Bs[nxt][lk+0][lr]    = rb0.x; Bs[nxt][lk+1][lr]    = rb0.y; Bs[nxt][lk+2][lr]    = rb0.z; Bs[nxt][lk+3][lr]    = rb0.w;
            Bs[nxt][lk+0][lr+64] = rb1.x; Bs[nxt][lk+1][lr+64] = rb1.y; Bs[nxt][lk+2][lr+64] = rb1.z; Bs[nxt][lk+3][lr+64] = rb1.w;
            __syncthreads();
        }
    }
    int row0 = blockIdx.y * 128;
    int col0 = blockIdx.x * 128;
    float4 bA = *(const float4*)(bias + col0 + bc0);
    float4 bB = *(const float4*)(bias + col0 + bc1);
#pragma unroll
    for (int i = 0; i < 8; i++) {
        int r = row0 + ((i < 4) ? (ar0 + i) : (ar1 + i - 4));
        float4 v0 = make_float4(acc[i][0] + bA.x, acc[i][1] + bA.y,
                                acc[i][2] + bA.z, acc[i][3] + bA.w);
        float4 v1 = make_float4(acc[i][4] + bB.x, acc[i][5] + bB.y,
                                acc[i][6] + bB.z, acc[i][7] + bB.w);
        *(float4*)(g_U + (size_t)r * D + col0 + bc0) = v0;
        *(float4*)(g_U + (size_t)r * D + col0 + bc1) = v1;
    }
}

__global__ __launch_bounds__(256)
void k_epilogue(float* __restrict__ out) {
    __shared__ float sM[D * NL2];
    __shared__ float sd[NL2];
    __shared__ int si1;
    int b = blockIdx.x;
    int tid = threadIdx.x;
    int lane = tid & 31;
    int w = tid >> 5;
    if (tid == 0) si1 = g_idx1[b];
    __syncthreads();
    int i1 = si1;
    {
        const float4* src = (const float4*)(g_Mall + (size_t)i1 * D * NL2);
        float4* dst = (float4*)sM;
        for (int t = tid; t < D * NL2 / 4; t += 256) dst[t] = src[t];
        if (tid < NL2) sd[tid] = g_dall[i1 * NL2 + tid];
    }
    __syncthreads();
    int rowBase = b * TLEN + blockIdx.y * 128 + w * 16;
    for (int r = 0; r < 16; r++) {
        int row = rowBase + r;
        const float4* up = (const float4*)(g_U + (size_t)row * D);
        float4 u0 = up[lane];
        float4 u1 = up[lane + 32];
        float h[8] = {u0.x, u0.y, u0.z, u0.w, u1.x, u1.y, u1.z, u1.w};
        float s = 0.f, q = 0.f;
#pragma unroll
        for (int e = 0; e < 8; e++) { s += h[e]; q += h[e]*h[e]; }
#pragma unroll
        for (int off = 16; off; off >>= 1) {
            s += __shfl_xor_sync(0xffffffffu, s, off);
            q += __shfl_xor_sync(0xffffffffu, q, off);
        }
        float mean = s * (1.f / 256.f);
        float var = q * (1.f / 256.f) - mean * mean;
        float rinv = rsqrtf(fmaxf(var, 0.f) + 1e-5f);
#pragma unroll
        for (int e = 0; e < 8; e++) h[e] = fmaxf((h[e] - mean) * rinv, 0.f);
        float acc = sd[lane];
#pragma unroll
        for (int e = 0; e < 8; e++) {
            int cb = (e < 4) ? e : (e + 124);
#pragma unroll 8
            for (int srcl = 0; srcl < 32; srcl++) {
                float hv = __shfl_sync(0xffffffffu, h[e], srcl);
                acc += hv * sM[(srcl * 4 + cb) * NL2 + lane];
            }
        }
        float best = acc; int bidx = lane;
#pragma unroll
        for (int off = 16; off; off >>= 1) {
            float ov = __shfl_xor_sync(0xffffffffu, best, off);
            int   oi = __shfl_xor_sync(0xffffffffu, bidx, off);
            if (ov > best || (ov == best && oi < bidx)) { best = ov; bidx = oi; }
        }
        const float4* trow = (const float4*)(g_table + (size_t)(i1 * NL2 + bidx) * D);
        float4* orow = (float4*)(out + (size_t)row * D);
        orow[lane]      = trow[lane];
        orow[lane + 32] = trow[lane + 32];
    }
}

extern "C" void kernel_launch(void* const* d_in, const int* in_sizes, int n_in,
                              void* d_out, int out_size) {
    const float* x   = (const float*)d_in[0];
    const float* Wg1 = (const float*)d_in[1];
    const float* bg1 = (const float*)d_in[2];
    const float* Wg2 = (const float*)d_in[3];
    const float* bg2 = (const float*)d_in[4];
    const float* Wl1 = (const float*)d_in[5];
    const float* bl1 = (const float*)d_in[6];
    const float* Wl2 = (const float*)d_in[7];
    const float* bl2 = (const float*)d_in[8];
    const float* Wp  = (const float*)d_in[9];
    const float* bp  = (const float*)d_in[10];
    const float* cb1 = (const float*)d_in[11];
    const float* Wtb = (const float*)d_in[12];
    const float* btb = (const float*)d_in[13];
    const float* Wfb = (const float*)d_in[14];
    const float* bfb = (const float*)d_in[15];
    const float* cb2 = (const float*)d_in[16];
    const float* Wf  = (const float*)d_in[17];
    const float* bf  = (const float*)d_in[18];
    float* out = (float*)d_out;

    k_wc      <<<64, 256>>>(Wtb, Wl2, bl2, btb);
    k_nck     <<<256, 64>>>(cb2);
    k_Md      <<<dim3(8, 32), 256>>>();
    k_table   <<<256, 256>>>(cb2, Wfb, bfb, cb1, Wf, bf);
    k_ginstats<<<64, 256>>>(x);
    k_global  <<<16, 256>>>(Wg1, bg1, Wg2, bg2, Wp, bp, cb1);
    k_sgemm   <<<dim3(2, 256), 256>>>(x, Wl1, bl1);
    k_epilogue<<<dim3(16, 16), 256>>>(out);
}